// round 15
// baseline (speedup 1.0000x reference)
#include <cuda_runtime.h>
#include <cuda_fp16.h>
#include <cstdint>

#define HIDDEN 512
#define MAX_NB 6
#define NB_MAXV  100000
#define NBP      100096   // padded to 128
#define NA_MAXV  50000
#define NAP      50048
#define KW1      160      // padded bond fdim (147 -> 160), 5 x 32
#define KWO      672      // padded concat (512 + 133 -> 672), 21 x 32

// ---------------- static scratch ----------------
__device__ __align__(128) float g_inp [(size_t)NBP * HIDDEN];   // raw pre-activation (also msg_0)
__device__ __align__(128) float g_msg [(size_t)NBP * HIDDEN];   // raw z_t (relu applied on read)
__device__ __align__(128) float g_amsg[(size_t)NAP * HIDDEN];
__device__ __align__(128) float g_hid [(size_t)NAP * HIDDEN];
__device__ __align__(128) __half g_Ahi[(size_t)NBP * HIDDEN];
__device__ __align__(128) __half g_Alo[(size_t)NBP * HIDDEN];
__device__ __align__(128) __half g_CatHi[(size_t)NAP * KWO];
__device__ __align__(128) __half g_CatLo[(size_t)NAP * KWO];
__device__ __align__(128) __half g_WiH[512 * KW1];
__device__ __align__(128) __half g_WhH[512 * 512];
__device__ __align__(128) __half g_WoH[512 * KWO];

// ---------------- helpers ----------------
__device__ __forceinline__ uint32_t smem_u32(const void* p) {
    uint32_t a;
    asm("{ .reg .u64 t; cvta.to.shared.u64 t, %1; cvt.u32.u64 %0, t; }" : "=r"(a) : "l"(p));
    return a;
}
#define CP_COMMIT() asm volatile("cp.async.commit_group;" ::: "memory")
#define CP_WAIT2()  asm volatile("cp.async.wait_group 2;" ::: "memory")

__device__ __forceinline__ void cp16(uint32_t dst, const void* src) {
    asm volatile("cp.async.cg.shared.global [%0], [%1], 16;" :: "r"(dst), "l"(src) : "memory");
}
__device__ __forceinline__ void ldm4(uint32_t* r, uint32_t addr) {
    asm volatile("ldmatrix.sync.aligned.m8n8.x4.shared.b16 {%0,%1,%2,%3}, [%4];"
        : "=r"(r[0]), "=r"(r[1]), "=r"(r[2]), "=r"(r[3]) : "r"(addr));
}
__device__ __forceinline__ void mma16816(float* c, const uint32_t* a, uint32_t b0, uint32_t b1) {
    asm volatile("mma.sync.aligned.m16n8k16.row.col.f32.f16.f16.f32 "
        "{%0,%1,%2,%3}, {%4,%5,%6,%7}, {%8,%9}, {%0,%1,%2,%3};"
        : "+f"(c[0]), "+f"(c[1]), "+f"(c[2]), "+f"(c[3])
        : "r"(a[0]), "r"(a[1]), "r"(a[2]), "r"(a[3]), "r"(b0), "r"(b1));
}
__device__ __forceinline__ void split2(float v, __half& h, __half& l) {
    h = __float2half_rn(v);
    l = __float2half_rn(v - __half2float(h));
}
__device__ __forceinline__ uint32_t pk(__half a, __half b) {
    __half2 t; t.x = a; t.y = b;
    return *reinterpret_cast<uint32_t*>(&t);
}

// ---------------- HMMA fp16 2-split GEMM ----------------
// C[M,512] = epilogue(A @ B^T), A: [Mpad, lda] fp16 hi/lo K-major,
// B: [512, ldb] single fp16 (weights pre-transposed, K-major).
// CTA 128x128x32, 256 thr, 8 warps (2M x 4N), warp tile 64x32.
// 4-stage cp.async pipeline (wait_group 2), XOR-swizzled 64B rows, 2 CTAs/SM.
#define MAT_SZ  (128 * 64)        // 8192 (128 rows x 32 fp16)
#define STG_SZ  (3 * MAT_SZ)      // 24576 : Ahi|Alo|B
#define NSTAGE  4
#define SMEM_SZ (NSTAGE * STG_SZ) // 98304 -> 2 CTAs/SM

__device__ __forceinline__ uint32_t swz(int row, uint32_t col) {
    return (uint32_t)(row * 64) + (col ^ (uint32_t)(((row >> 1) & 3) << 4));
}

__device__ __forceinline__ void load_stage(
    uint32_t sdst, int tid,
    const __half* Ah0, const __half* Al0, int lda,
    const __half* B0, int ldb, int k0)
{
    // 3 arrays x 128 rows x 4 x 16B = 1536 slots, 6 per thread
#pragma unroll
    for (int i = 0; i < 6; ++i) {
        int c = i * 256 + tid;
        int arr = c >> 9, idx = c & 511, row = idx >> 2, j = idx & 3;
        const __half* src; int ld;
        if (arr == 0)      { src = Ah0; ld = lda; }
        else if (arr == 1) { src = Al0; ld = lda; }
        else               { src = B0;  ld = ldb; }
        cp16(sdst + arr * MAT_SZ + swz(row, j * 16),
             src + (size_t)row * ld + k0 + j * 8);
    }
}

__device__ __forceinline__ void compute_chunk(
    uint32_t sb, int wm, int wn, int lane, float (&acc)[4][4][4])
{
    const int lrow = lane & 15;
    const uint32_t kb0 = ((lane >> 4) & 1) * 16;
#pragma unroll
    for (int ks = 0; ks < 2; ++ks) {
        const uint32_t kb = ks * 32 + kb0;
        uint32_t ah[4][4], al[4][4];
#pragma unroll
        for (int mt = 0; mt < 4; ++mt) {
            int row = wm + mt * 16 + lrow;
            uint32_t rb = swz(row, kb);
            ldm4(ah[mt], sb + rb);
            ldm4(al[mt], sb + MAT_SZ + rb);
        }
        uint32_t bh[2][4];
#pragma unroll
        for (int nt = 0; nt < 2; ++nt) {
            int row = wn + nt * 16 + lrow;
            ldm4(bh[nt], sb + 2 * MAT_SZ + swz(row, kb));
        }
#pragma unroll
        for (int s = 0; s < 2; ++s)
#pragma unroll
            for (int mt = 0; mt < 4; ++mt)
#pragma unroll
                for (int n8 = 0; n8 < 4; ++n8) {
                    const uint32_t* a = (s == 0) ? ah[mt] : al[mt];
                    uint32_t b0 = bh[n8 >> 1][n8 & 1], b1 = bh[n8 >> 1][(n8 & 1) + 2];
                    mma16816(acc[mt][n8], a, b0, b1);
                }
    }
}

// MODE 0: Cout = acc (raw)            (gemm0: inp)
// MODE 1: Cout = acc + Cin (raw)      (Wh: z_t; relu applied by consumers)
// MODE 2: Cout = relu(acc + bias)     (Wo: atom hiddens)
template<int MODE>
__global__ __launch_bounds__(256, 2)
void gemm_hmma2(const __half* __restrict__ Ahi, const __half* __restrict__ Alo, int lda,
                const __half* __restrict__ B, int ldb,
                int K, const float* __restrict__ Cin, const float* __restrict__ bias,
                float* __restrict__ Cout)
{
    extern __shared__ char smem[];
    const uint32_t sbase = smem_u32(smem);
    const int tid = threadIdx.x, lane = tid & 31, wid = tid >> 5;
    const int wm = (wid & 1) * 64, wn = (wid >> 1) * 32;
    const size_t bm = (size_t)blockIdx.y * 128;
    const int bn = blockIdx.x * 128;

    const __half* Ah0 = Ahi + bm * lda;
    const __half* Al0 = Alo + bm * lda;
    const __half* B0  = B + (size_t)bn * ldb;

    const int nc = K >> 5;       // chunks of 32
    float acc[4][4][4];
#pragma unroll
    for (int a = 0; a < 4; ++a)
#pragma unroll
        for (int b = 0; b < 4; ++b)
#pragma unroll
            for (int q = 0; q < 4; ++q) acc[a][b][q] = 0.f;

    // prologue: fill 3 stages (empty commits keep group accounting uniform)
    load_stage(sbase, tid, Ah0, Al0, lda, B0, ldb, 0);
    CP_COMMIT();
    if (nc > 1) load_stage(sbase + STG_SZ, tid, Ah0, Al0, lda, B0, ldb, 32);
    CP_COMMIT();
    if (nc > 2) load_stage(sbase + 2 * STG_SZ, tid, Ah0, Al0, lda, B0, ldb, 64);
    CP_COMMIT();

    int buf = 0;
    for (int c = 0; c < nc; ++c) {
        CP_WAIT2();                 // stage c landed (<=2 groups pending)
        __syncthreads();            // all cps visible; readers of refill target are done
        if (c + 3 < nc) {
            int nb = buf + 3; if (nb >= NSTAGE) nb -= NSTAGE;
            load_stage(sbase + nb * STG_SZ, tid,
                       Ah0, Al0, lda, B0, ldb, (c + 3) << 5);
        }
        CP_COMMIT();
        compute_chunk(sbase + buf * STG_SZ, wm, wn, lane, acc);
        if (++buf == NSTAGE) buf = 0;
    }

    // epilogue: acc[mt][nt][{0,1}] = rows r, cols c0,c0+1; [{2,3}] = rows r+8
    const int r0 = lane >> 2, c0 = (lane & 3) * 2;
#pragma unroll
    for (int mt = 0; mt < 4; ++mt) {
#pragma unroll
        for (int half = 0; half < 2; ++half) {
            const size_t gm = bm + wm + mt * 16 + r0 + half * 8;
            const size_t rowbase = gm * HIDDEN + bn + wn + c0;
#pragma unroll
            for (int nt = 0; nt < 4; ++nt) {
                float2 v = {acc[mt][nt][half * 2], acc[mt][nt][half * 2 + 1]};
                const size_t idx = rowbase + nt * 8;
                if (MODE == 1) {
                    float2 ci = *reinterpret_cast<const float2*>(Cin + idx);
                    v.x += ci.x; v.y += ci.y;
                }
                if (MODE == 2) {
                    float2 bi = *reinterpret_cast<const float2*>(bias + bn + wn + c0 + nt * 8);
                    v.x = fmaxf(v.x + bi.x, 0.f);
                    v.y = fmaxf(v.y + bi.y, 0.f);
                }
                *reinterpret_cast<float2*>(Cout + idx) = v;
            }
        }
    }
}

// ---------------- aggregation / combine (relu applied on read) ----------------
// 2 atoms per 256-thread block: deeper per-block MLP, half the blocks.
__global__ __launch_bounds__(256)
void aggregate_f32(const float* __restrict__ msg, const int* __restrict__ a2b,
                   float* __restrict__ amsg, int n_atoms)
{
    const int a = blockIdx.x * 2 + (threadIdx.x >> 7);
    const int h4 = threadIdx.x & 127;
    if (a >= n_atoms) return;
    const int* nb = a2b + a * MAX_NB;
    float4 sum = {0.f, 0.f, 0.f, 0.f};
#pragma unroll
    for (int k = 0; k < MAX_NB; ++k) {
        const float4 m = *reinterpret_cast<const float4*>(msg + (size_t)nb[k] * HIDDEN + h4 * 4);
        sum.x += fmaxf(m.x, 0.f); sum.y += fmaxf(m.y, 0.f);
        sum.z += fmaxf(m.z, 0.f); sum.w += fmaxf(m.w, 0.f);
    }
    *reinterpret_cast<float4*>(amsg + (size_t)a * HIDDEN + h4 * 4) = sum;
}

__global__ __launch_bounds__(256)
void aggregate_f16(const float* __restrict__ msg, const int* __restrict__ a2b,
                   __half* __restrict__ dhi, __half* __restrict__ dlo,
                   int n_atoms)
{
    const int a = blockIdx.x * 2 + (threadIdx.x >> 7);
    const int h4 = threadIdx.x & 127;
    if (a >= NAP) return;
    float4 sum = {0.f, 0.f, 0.f, 0.f};
    if (a < n_atoms) {
        const int* nb = a2b + a * MAX_NB;
#pragma unroll
        for (int k = 0; k < MAX_NB; ++k) {
            const float4 m = *reinterpret_cast<const float4*>(msg + (size_t)nb[k] * HIDDEN + h4 * 4);
            sum.x += fmaxf(m.x, 0.f); sum.y += fmaxf(m.y, 0.f);
            sum.z += fmaxf(m.z, 0.f); sum.w += fmaxf(m.w, 0.f);
        }
    }
    __half h0, l0, h1, l1, h2, l2, h3, l3;
    split2(sum.x, h0, l0); split2(sum.y, h1, l1);
    split2(sum.z, h2, l2); split2(sum.w, h3, l3);
    uint2 hv = {pk(h0, h1), pk(h2, h3)};
    uint2 lv = {pk(l0, l1), pk(l2, l3)};
    *reinterpret_cast<uint2*>(dhi + (size_t)a * KWO + h4 * 4) = hv;
    *reinterpret_cast<uint2*>(dlo + (size_t)a * KWO + h4 * 4) = lv;
}

// 2 bonds per 256-thread block.
__global__ __launch_bounds__(256)
void combine_k(const float* __restrict__ amsg, const float* __restrict__ msg,
               const int* __restrict__ b2a, const int* __restrict__ b2revb,
               __half* __restrict__ dhi, __half* __restrict__ dlo,
               int n_bonds)
{
    const int b = blockIdx.x * 2 + (threadIdx.x >> 7);
    const int h4 = threadIdx.x & 127;
    if (b >= NBP) return;
    float4 v = {0.f, 0.f, 0.f, 0.f};
    if (b < n_bonds) {
        const int a = b2a[b], rb = b2revb[b];
        const float4 am = *reinterpret_cast<const float4*>(amsg + (size_t)a * HIDDEN + h4 * 4);
        const float4 rm = *reinterpret_cast<const float4*>(msg + (size_t)rb * HIDDEN + h4 * 4);
        v.x = am.x - fmaxf(rm.x, 0.f); v.y = am.y - fmaxf(rm.y, 0.f);
        v.z = am.z - fmaxf(rm.z, 0.f); v.w = am.w - fmaxf(rm.w, 0.f);
    }
    __half h0, l0, h1, l1, h2, l2, h3, l3;
    split2(v.x, h0, l0); split2(v.y, h1, l1);
    split2(v.z, h2, l2); split2(v.w, h3, l3);
    uint2 hv = {pk(h0, h1), pk(h2, h3)};
    uint2 lv = {pk(l0, l1), pk(l2, l3)};
    *reinterpret_cast<uint2*>(dhi + (size_t)b * HIDDEN + h4 * 4) = hv;
    *reinterpret_cast<uint2*>(dlo + (size_t)b * HIDDEN + h4 * 4) = lv;
}

// ---------------- single merged conversion kernel ----------------
// Weights -> single fp16 transposed; rows -> fp16 hi/lo.
__global__ __launch_bounds__(256)
void conv_all(const float* __restrict__ Wi, const float* __restrict__ Wh,
              const float* __restrict__ Wo,
              const float* __restrict__ f_bonds, const float* __restrict__ f_atoms,
              __half* __restrict__ WiH, __half* __restrict__ WhH, __half* __restrict__ WoH,
              __half* __restrict__ Ahi, __half* __restrict__ Alo,
              __half* __restrict__ CatHi, __half* __restrict__ CatLo,
              int bond_fdim, int atom_fdim, int n_bonds, int n_atoms)
{
    int idx = blockIdx.x * 256 + threadIdx.x;
    const int w0 = 512 * KW1, w1 = 512 * 512, w2 = 512 * 512, w3 = 512 * KW1;
    const int wtot = w0 + w1 + w2 + w3;
    if (idx < wtot) {
        const float* W; __half* dh;
        int kcount, Ksrc, ldd, kofs;
        if (idx < w0) {
            W = Wi; dh = WiH; kcount = KW1; Ksrc = bond_fdim; ldd = KW1; kofs = 0;
        } else if ((idx -= w0) < w1) {
            W = Wh; dh = WhH; kcount = 512; Ksrc = 512; ldd = 512; kofs = 0;
        } else if ((idx -= w1) < w2) {
            W = Wo + (size_t)atom_fdim * 512; dh = WoH;
            kcount = 512; Ksrc = 512; ldd = KWO; kofs = 0;
        } else {
            idx -= w2;
            W = Wo; dh = WoH; kcount = KW1; Ksrc = atom_fdim; ldd = KWO; kofs = 512;
        }
        int n = idx / kcount, kk = idx % kcount;
        float v = (kk < Ksrc) ? W[(size_t)kk * 512 + n] : 0.f;
        dh[(size_t)n * ldd + kofs + kk] = __float2half_rn(v);
        return;
    }
    idx -= wtot;
    const float* src; __half *dh, *dl;
    int n_rows, fd, ldd, cofs, r, c4;
    if (idx < NBP * 40) {
        src = f_bonds; n_rows = n_bonds; fd = bond_fdim;
        dh = Ahi; dl = Alo; ldd = HIDDEN; cofs = 0;
        r = idx / 40; c4 = idx % 40;
    } else if ((idx -= NBP * 40) < NAP * 40) {
        src = f_atoms; n_rows = n_atoms; fd = atom_fdim;
        dh = CatHi; dl = CatLo; ldd = KWO; cofs = 512;
        r = idx / 40; c4 = idx % 40;
    } else return;
    float v[4];
#pragma unroll
    for (int i = 0; i < 4; ++i) {
        int c = c4 * 4 + i;
        v[i] = (r < n_rows && c < fd) ? src[(size_t)r * fd + c] : 0.f;
    }
    __half h0, l0, h1, l1, h2, l2, h3, l3;
    split2(v[0], h0, l0); split2(v[1], h1, l1);
    split2(v[2], h2, l2); split2(v[3], h3, l3);
    uint2 hv = {pk(h0, h1), pk(h2, h3)};
    uint2 lv = {pk(l0, l1), pk(l2, l3)};
    *reinterpret_cast<uint2*>(dh + (size_t)r * ldd + cofs + c4 * 4) = hv;
    *reinterpret_cast<uint2*>(dl + (size_t)r * ldd + cofs + c4 * 4) = lv;
}

__global__ __launch_bounds__(128)
void segmean_kernel(const float* __restrict__ hid, const int* __restrict__ mol_ids,
                    float* __restrict__ out, int n_atoms)
{
    const int m = blockIdx.x, h4 = threadIdx.x;
    int lo = 0, hi = n_atoms;
    while (lo < hi) { int mid = (lo + hi) >> 1; if (mol_ids[mid] < m) lo = mid + 1; else hi = mid; }
    const int start = lo;
    hi = n_atoms;
    while (lo < hi) { int mid = (lo + hi) >> 1; if (mol_ids[mid] < m + 1) lo = mid + 1; else hi = mid; }
    const int end = lo;
    const int cnt = end - start;
    const float inv = cnt > 0 ? 1.f / (float)cnt : 0.f;
    float4 s = {0.f, 0.f, 0.f, 0.f};
    for (int a = start; a < end; ++a) {
        const float4 v = *reinterpret_cast<const float4*>(hid + (size_t)a * HIDDEN + h4 * 4);
        s.x += v.x; s.y += v.y; s.z += v.z; s.w += v.w;
    }
    s.x *= inv; s.y *= inv; s.z *= inv; s.w *= inv;
    *reinterpret_cast<float4*>(out + (size_t)m * HIDDEN + h4 * 4) = s;
}

// ---------------- launch ----------------
extern "C" void kernel_launch(void* const* d_in, const int* in_sizes, int n_in,
                              void* d_out, int out_size)
{
    const float* f_atoms = (const float*)d_in[0];
    const float* f_bonds = (const float*)d_in[1];
    const int*   a2b     = (const int*)  d_in[2];
    const int*   b2a     = (const int*)  d_in[3];
    const int*   b2revb  = (const int*)  d_in[4];
    const int*   mol_ids = (const int*)  d_in[5];
    const float* W_i     = (const float*)d_in[6];
    const float* W_h     = (const float*)d_in[7];
    const float* W_o     = (const float*)d_in[8];
    const float* b_o     = (const float*)d_in[9];

    const int n_atoms   = in_sizes[5];
    const int n_bonds   = in_sizes[3];
    const int bond_fdim = in_sizes[6] / HIDDEN;            // 147
    const int atom_fdim = in_sizes[8] / HIDDEN - HIDDEN;   // 133
    const int n_mols    = out_size / HIDDEN;
    float* out = (float*)d_out;

    float *p_inp, *p_msg, *p_amsg, *p_hid;
    __half *p_Ahi, *p_Alo, *p_CatHi, *p_CatLo, *p_WiH, *p_WhH, *p_WoH;
    cudaGetSymbolAddress((void**)&p_inp,  g_inp);
    cudaGetSymbolAddress((void**)&p_msg,  g_msg);
    cudaGetSymbolAddress((void**)&p_amsg, g_amsg);
    cudaGetSymbolAddress((void**)&p_hid,  g_hid);
    cudaGetSymbolAddress((void**)&p_Ahi,  g_Ahi);
    cudaGetSymbolAddress((void**)&p_Alo,  g_Alo);
    cudaGetSymbolAddress((void**)&p_CatHi, g_CatHi);
    cudaGetSymbolAddress((void**)&p_CatLo, g_CatLo);
    cudaGetSymbolAddress((void**)&p_WiH,  g_WiH);
    cudaGetSymbolAddress((void**)&p_WhH,  g_WhH);
    cudaGetSymbolAddress((void**)&p_WoH,  g_WoH);

    cudaFuncSetAttribute(gemm_hmma2<0>, cudaFuncAttributeMaxDynamicSharedMemorySize, SMEM_SZ);
    cudaFuncSetAttribute(gemm_hmma2<1>, cudaFuncAttributeMaxDynamicSharedMemorySize, SMEM_SZ);
    cudaFuncSetAttribute(gemm_hmma2<2>, cudaFuncAttributeMaxDynamicSharedMemorySize, SMEM_SZ);

    // [0] all conversions (weights + rows) in one launch
    const int conv_elems = 512 * (KW1 + 512 + 512 + KW1) + (NBP + NAP) * 40;
    conv_all<<<(conv_elems + 255) / 256, 256>>>(
        W_i, W_h, W_o, f_bonds, f_atoms,
        p_WiH, p_WhH, p_WoH,
        p_Ahi, p_Alo, p_CatHi, p_CatLo,
        bond_fdim, atom_fdim, n_bonds, n_atoms);

    // [1] GEMM0: inp = f_bonds @ W_i  (raw; msg_0 = relu(inp) applied on read)
    gemm_hmma2<0><<<dim3(4, NBP / 128), 256, SMEM_SZ>>>(
        p_Ahi, p_Alo, HIDDEN, p_WiH, KW1, KW1,
        nullptr, nullptr, p_inp);

    // [2..] 4 message-passing iterations; z_t stored raw, relu on read
    const float* curmsg = p_inp;
    for (int it = 0; it < 4; ++it) {
        aggregate_f32<<<(n_atoms + 1) / 2, 256>>>(curmsg, a2b, p_amsg, n_atoms);
        combine_k<<<NBP / 2, 256>>>(p_amsg, curmsg, b2a, b2revb, p_Ahi, p_Alo, n_bonds);
        gemm_hmma2<1><<<dim3(4, NBP / 128), 256, SMEM_SZ>>>(
            p_Ahi, p_Alo, HIDDEN, p_WhH, 512, 512,
            p_inp, nullptr, p_msg);
        curmsg = p_msg;
    }

    // final aggregation (relu on read) -> concat A cols 0..511
    aggregate_f16<<<NAP / 2, 256>>>(p_msg, a2b, p_CatHi, p_CatLo, n_atoms);

    // atom_hiddens = relu([amsg | f_atoms] @ Wo_cat + b_o)
    gemm_hmma2<2><<<dim3(4, NAP / 128), 256, SMEM_SZ>>>(
        p_CatHi, p_CatLo, KWO, p_WoH, KWO, KWO,
        nullptr, b_o, p_hid);

    segmean_kernel<<<n_mols, 128>>>(p_hid, mol_ids, out, n_atoms);
}

// round 16
// speedup vs baseline: 1.0049x; 1.0049x over previous
#include <cuda_runtime.h>
#include <cuda_fp16.h>
#include <cstdint>

#define HIDDEN 512
#define MAX_NB 6
#define NB_MAXV  100000
#define NBP      100096   // padded to 128
#define NA_MAXV  50000
#define NAP      50048
#define KW1      160      // padded bond fdim (147 -> 160), 5 x 32
#define KWO      672      // padded concat (512 + 133 -> 672), 21 x 32

// ---------------- static scratch ----------------
__device__ __align__(128) float g_inp [(size_t)NBP * HIDDEN];   // raw pre-activation (also msg_0)
__device__ __align__(128) float g_msg [(size_t)NBP * HIDDEN];   // raw z_t (relu applied on read)
__device__ __align__(128) float g_amsg[(size_t)NAP * HIDDEN];
__device__ __align__(128) float g_hid [(size_t)NAP * HIDDEN];
__device__ __align__(128) __half g_Ahi[(size_t)NBP * HIDDEN];
__device__ __align__(128) __half g_Alo[(size_t)NBP * HIDDEN];
__device__ __align__(128) __half g_CatHi[(size_t)NAP * KWO];
__device__ __align__(128) __half g_CatLo[(size_t)NAP * KWO];
__device__ __align__(128) __half g_WiH[512 * KW1];
__device__ __align__(128) __half g_WhH[512 * 512];
__device__ __align__(128) __half g_WoH[512 * KWO];

// ---------------- helpers ----------------
__device__ __forceinline__ uint32_t smem_u32(const void* p) {
    uint32_t a;
    asm("{ .reg .u64 t; cvta.to.shared.u64 t, %1; cvt.u32.u64 %0, t; }" : "=r"(a) : "l"(p));
    return a;
}
#define CP_COMMIT() asm volatile("cp.async.commit_group;" ::: "memory")
#define CP_WAIT2()  asm volatile("cp.async.wait_group 2;" ::: "memory")

__device__ __forceinline__ void cp16(uint32_t dst, const void* src) {
    asm volatile("cp.async.cg.shared.global [%0], [%1], 16;" :: "r"(dst), "l"(src) : "memory");
}
__device__ __forceinline__ void ldm4(uint32_t* r, uint32_t addr) {
    asm volatile("ldmatrix.sync.aligned.m8n8.x4.shared.b16 {%0,%1,%2,%3}, [%4];"
        : "=r"(r[0]), "=r"(r[1]), "=r"(r[2]), "=r"(r[3]) : "r"(addr));
}
__device__ __forceinline__ void mma16816(float* c, const uint32_t* a, uint32_t b0, uint32_t b1) {
    asm volatile("mma.sync.aligned.m16n8k16.row.col.f32.f16.f16.f32 "
        "{%0,%1,%2,%3}, {%4,%5,%6,%7}, {%8,%9}, {%0,%1,%2,%3};"
        : "+f"(c[0]), "+f"(c[1]), "+f"(c[2]), "+f"(c[3])
        : "r"(a[0]), "r"(a[1]), "r"(a[2]), "r"(a[3]), "r"(b0), "r"(b1));
}
__device__ __forceinline__ void split2(float v, __half& h, __half& l) {
    h = __float2half_rn(v);
    l = __float2half_rn(v - __half2float(h));
}
__device__ __forceinline__ uint32_t pk(__half a, __half b) {
    __half2 t; t.x = a; t.y = b;
    return *reinterpret_cast<uint32_t*>(&t);
}

// ---------------- HMMA fp16 2-split GEMM ----------------
// C[M,512] = epilogue(A @ B^T), A: [Mpad, lda] fp16 hi/lo K-major,
// B: [512, ldb] single fp16 (weights pre-transposed, K-major).
// CTA 128x128x32, 256 thr, 8 warps (2M x 4N), warp tile 64x32.
// 4-stage cp.async pipeline (wait_group 2), XOR-swizzled 64B rows, 2 CTAs/SM.
#define MAT_SZ  (128 * 64)        // 8192 (128 rows x 32 fp16)
#define STG_SZ  (3 * MAT_SZ)      // 24576 : Ahi|Alo|B
#define NSTAGE  4
#define SMEM_SZ (NSTAGE * STG_SZ) // 98304 -> 2 CTAs/SM

__device__ __forceinline__ uint32_t swz(int row, uint32_t col) {
    return (uint32_t)(row * 64) + (col ^ (uint32_t)(((row >> 1) & 3) << 4));
}

__device__ __forceinline__ void load_stage(
    uint32_t sdst, int tid,
    const __half* Ah0, const __half* Al0, int lda,
    const __half* B0, int ldb, int k0)
{
    // 3 arrays x 128 rows x 4 x 16B = 1536 slots, 6 per thread
#pragma unroll
    for (int i = 0; i < 6; ++i) {
        int c = i * 256 + tid;
        int arr = c >> 9, idx = c & 511, row = idx >> 2, j = idx & 3;
        const __half* src; int ld;
        if (arr == 0)      { src = Ah0; ld = lda; }
        else if (arr == 1) { src = Al0; ld = lda; }
        else               { src = B0;  ld = ldb; }
        cp16(sdst + arr * MAT_SZ + swz(row, j * 16),
             src + (size_t)row * ld + k0 + j * 8);
    }
}

__device__ __forceinline__ void compute_chunk(
    uint32_t sb, int wm, int wn, int lane, float (&acc)[4][4][4])
{
    const int lrow = lane & 15;
    const uint32_t kb0 = ((lane >> 4) & 1) * 16;
#pragma unroll
    for (int ks = 0; ks < 2; ++ks) {
        const uint32_t kb = ks * 32 + kb0;
        uint32_t ah[4][4], al[4][4];
#pragma unroll
        for (int mt = 0; mt < 4; ++mt) {
            int row = wm + mt * 16 + lrow;
            uint32_t rb = swz(row, kb);
            ldm4(ah[mt], sb + rb);
            ldm4(al[mt], sb + MAT_SZ + rb);
        }
        uint32_t bh[2][4];
#pragma unroll
        for (int nt = 0; nt < 2; ++nt) {
            int row = wn + nt * 16 + lrow;
            ldm4(bh[nt], sb + 2 * MAT_SZ + swz(row, kb));
        }
#pragma unroll
        for (int s = 0; s < 2; ++s)
#pragma unroll
            for (int mt = 0; mt < 4; ++mt)
#pragma unroll
                for (int n8 = 0; n8 < 4; ++n8) {
                    const uint32_t* a = (s == 0) ? ah[mt] : al[mt];
                    uint32_t b0 = bh[n8 >> 1][n8 & 1], b1 = bh[n8 >> 1][(n8 & 1) + 2];
                    mma16816(acc[mt][n8], a, b0, b1);
                }
    }
}

// MODE 0: Cout = acc (raw)            (gemm0: inp)
// MODE 1: Cout = acc + Cin (raw)      (Wh: z_t; relu applied by consumers)
// MODE 2: Cout = relu(acc + bias)     (Wo: atom hiddens)
template<int MODE>
__global__ __launch_bounds__(256, 2)
void gemm_hmma2(const __half* __restrict__ Ahi, const __half* __restrict__ Alo, int lda,
                const __half* __restrict__ B, int ldb,
                int K, const float* __restrict__ Cin, const float* __restrict__ bias,
                float* __restrict__ Cout)
{
    extern __shared__ char smem[];
    const uint32_t sbase = smem_u32(smem);
    const int tid = threadIdx.x, lane = tid & 31, wid = tid >> 5;
    const int wm = (wid & 1) * 64, wn = (wid >> 1) * 32;
    const size_t bm = (size_t)blockIdx.y * 128;
    const int bn = blockIdx.x * 128;

    const __half* Ah0 = Ahi + bm * lda;
    const __half* Al0 = Alo + bm * lda;
    const __half* B0  = B + (size_t)bn * ldb;

    const int nc = K >> 5;       // chunks of 32
    float acc[4][4][4];
#pragma unroll
    for (int a = 0; a < 4; ++a)
#pragma unroll
        for (int b = 0; b < 4; ++b)
#pragma unroll
            for (int q = 0; q < 4; ++q) acc[a][b][q] = 0.f;

    // prologue: fill 3 stages (empty commits keep group accounting uniform)
    load_stage(sbase, tid, Ah0, Al0, lda, B0, ldb, 0);
    CP_COMMIT();
    if (nc > 1) load_stage(sbase + STG_SZ, tid, Ah0, Al0, lda, B0, ldb, 32);
    CP_COMMIT();
    if (nc > 2) load_stage(sbase + 2 * STG_SZ, tid, Ah0, Al0, lda, B0, ldb, 64);
    CP_COMMIT();

    int buf = 0;
    for (int c = 0; c < nc; ++c) {
        CP_WAIT2();                 // stage c landed (<=2 groups pending)
        __syncthreads();            // all cps visible; readers of refill target are done
        if (c + 3 < nc) {
            int nb = buf + 3; if (nb >= NSTAGE) nb -= NSTAGE;
            load_stage(sbase + nb * STG_SZ, tid,
                       Ah0, Al0, lda, B0, ldb, (c + 3) << 5);
        }
        CP_COMMIT();
        compute_chunk(sbase + buf * STG_SZ, wm, wn, lane, acc);
        if (++buf == NSTAGE) buf = 0;
    }

    // epilogue: acc[mt][nt][{0,1}] = rows r, cols c0,c0+1; [{2,3}] = rows r+8
    const int r0 = lane >> 2, c0 = (lane & 3) * 2;
#pragma unroll
    for (int mt = 0; mt < 4; ++mt) {
#pragma unroll
        for (int half = 0; half < 2; ++half) {
            const size_t gm = bm + wm + mt * 16 + r0 + half * 8;
            const size_t rowbase = gm * HIDDEN + bn + wn + c0;
#pragma unroll
            for (int nt = 0; nt < 4; ++nt) {
                float2 v = {acc[mt][nt][half * 2], acc[mt][nt][half * 2 + 1]};
                const size_t idx = rowbase + nt * 8;
                if (MODE == 1) {
                    float2 ci = *reinterpret_cast<const float2*>(Cin + idx);
                    v.x += ci.x; v.y += ci.y;
                }
                if (MODE == 2) {
                    float2 bi = *reinterpret_cast<const float2*>(bias + bn + wn + c0 + nt * 8);
                    v.x = fmaxf(v.x + bi.x, 0.f);
                    v.y = fmaxf(v.y + bi.y, 0.f);
                }
                *reinterpret_cast<float2*>(Cout + idx) = v;
            }
        }
    }
}

// ---------------- aggregation / combine (relu applied on read) ----------------
__global__ __launch_bounds__(128)
void aggregate_f32(const float* __restrict__ msg, const int* __restrict__ a2b,
                   float* __restrict__ amsg)
{
    const int a = blockIdx.x, h4 = threadIdx.x;
    const int* nb = a2b + a * MAX_NB;
    float4 sum = {0.f, 0.f, 0.f, 0.f};
#pragma unroll
    for (int k = 0; k < MAX_NB; ++k) {
        const float4 m = *reinterpret_cast<const float4*>(msg + (size_t)nb[k] * HIDDEN + h4 * 4);
        sum.x += fmaxf(m.x, 0.f); sum.y += fmaxf(m.y, 0.f);
        sum.z += fmaxf(m.z, 0.f); sum.w += fmaxf(m.w, 0.f);
    }
    *reinterpret_cast<float4*>(amsg + (size_t)a * HIDDEN + h4 * 4) = sum;
}

__global__ __launch_bounds__(128)
void aggregate_f16(const float* __restrict__ msg, const int* __restrict__ a2b,
                   __half* __restrict__ dhi, __half* __restrict__ dlo,
                   int n_atoms)
{
    const int a = blockIdx.x, h4 = threadIdx.x;
    float4 sum = {0.f, 0.f, 0.f, 0.f};
    if (a < n_atoms) {
        const int* nb = a2b + a * MAX_NB;
#pragma unroll
        for (int k = 0; k < MAX_NB; ++k) {
            const float4 m = *reinterpret_cast<const float4*>(msg + (size_t)nb[k] * HIDDEN + h4 * 4);
            sum.x += fmaxf(m.x, 0.f); sum.y += fmaxf(m.y, 0.f);
            sum.z += fmaxf(m.z, 0.f); sum.w += fmaxf(m.w, 0.f);
        }
    }
    __half h0, l0, h1, l1, h2, l2, h3, l3;
    split2(sum.x, h0, l0); split2(sum.y, h1, l1);
    split2(sum.z, h2, l2); split2(sum.w, h3, l3);
    uint2 hv = {pk(h0, h1), pk(h2, h3)};
    uint2 lv = {pk(l0, l1), pk(l2, l3)};
    *reinterpret_cast<uint2*>(dhi + (size_t)a * KWO + h4 * 4) = hv;
    *reinterpret_cast<uint2*>(dlo + (size_t)a * KWO + h4 * 4) = lv;
}

__global__ __launch_bounds__(128)
void combine_k(const float* __restrict__ amsg, const float* __restrict__ msg,
               const int* __restrict__ b2a, const int* __restrict__ b2revb,
               __half* __restrict__ dhi, __half* __restrict__ dlo,
               int n_bonds)
{
    const int b = blockIdx.x, h4 = threadIdx.x;
    float4 v = {0.f, 0.f, 0.f, 0.f};
    if (b < n_bonds) {
        const int a = b2a[b], rb = b2revb[b];
        const float4 am = *reinterpret_cast<const float4*>(amsg + (size_t)a * HIDDEN + h4 * 4);
        const float4 rm = *reinterpret_cast<const float4*>(msg + (size_t)rb * HIDDEN + h4 * 4);
        v.x = am.x - fmaxf(rm.x, 0.f); v.y = am.y - fmaxf(rm.y, 0.f);
        v.z = am.z - fmaxf(rm.z, 0.f); v.w = am.w - fmaxf(rm.w, 0.f);
    }
    __half h0, l0, h1, l1, h2, l2, h3, l3;
    split2(v.x, h0, l0); split2(v.y, h1, l1);
    split2(v.z, h2, l2); split2(v.w, h3, l3);
    uint2 hv = {pk(h0, h1), pk(h2, h3)};
    uint2 lv = {pk(l0, l1), pk(l2, l3)};
    *reinterpret_cast<uint2*>(dhi + (size_t)b * HIDDEN + h4 * 4) = hv;
    *reinterpret_cast<uint2*>(dlo + (size_t)b * HIDDEN + h4 * 4) = lv;
}

// ---------------- single merged conversion kernel ----------------
// Weights -> single fp16 transposed; rows -> fp16 hi/lo.
__global__ __launch_bounds__(256)
void conv_all(const float* __restrict__ Wi, const float* __restrict__ Wh,
              const float* __restrict__ Wo,
              const float* __restrict__ f_bonds, const float* __restrict__ f_atoms,
              __half* __restrict__ WiH, __half* __restrict__ WhH, __half* __restrict__ WoH,
              __half* __restrict__ Ahi, __half* __restrict__ Alo,
              __half* __restrict__ CatHi, __half* __restrict__ CatLo,
              int bond_fdim, int atom_fdim, int n_bonds, int n_atoms)
{
    int idx = blockIdx.x * 256 + threadIdx.x;
    const int w0 = 512 * KW1, w1 = 512 * 512, w2 = 512 * 512, w3 = 512 * KW1;
    const int wtot = w0 + w1 + w2 + w3;
    if (idx < wtot) {
        const float* W; __half* dh;
        int kcount, Ksrc, ldd, kofs;
        if (idx < w0) {
            W = Wi; dh = WiH; kcount = KW1; Ksrc = bond_fdim; ldd = KW1; kofs = 0;
        } else if ((idx -= w0) < w1) {
            W = Wh; dh = WhH; kcount = 512; Ksrc = 512; ldd = 512; kofs = 0;
        } else if ((idx -= w1) < w2) {
            W = Wo + (size_t)atom_fdim * 512; dh = WoH;
            kcount = 512; Ksrc = 512; ldd = KWO; kofs = 0;
        } else {
            idx -= w2;
            W = Wo; dh = WoH; kcount = KW1; Ksrc = atom_fdim; ldd = KWO; kofs = 512;
        }
        int n = idx / kcount, kk = idx % kcount;
        float v = (kk < Ksrc) ? W[(size_t)kk * 512 + n] : 0.f;
        dh[(size_t)n * ldd + kofs + kk] = __float2half_rn(v);
        return;
    }
    idx -= wtot;
    const float* src; __half *dh, *dl;
    int n_rows, fd, ldd, cofs, r, c4;
    if (idx < NBP * 40) {
        src = f_bonds; n_rows = n_bonds; fd = bond_fdim;
        dh = Ahi; dl = Alo; ldd = HIDDEN; cofs = 0;
        r = idx / 40; c4 = idx % 40;
    } else if ((idx -= NBP * 40) < NAP * 40) {
        src = f_atoms; n_rows = n_atoms; fd = atom_fdim;
        dh = CatHi; dl = CatLo; ldd = KWO; cofs = 512;
        r = idx / 40; c4 = idx % 40;
    } else return;
    float v[4];
#pragma unroll
    for (int i = 0; i < 4; ++i) {
        int c = c4 * 4 + i;
        v[i] = (r < n_rows && c < fd) ? src[(size_t)r * fd + c] : 0.f;
    }
    __half h0, l0, h1, l1, h2, l2, h3, l3;
    split2(v[0], h0, l0); split2(v[1], h1, l1);
    split2(v[2], h2, l2); split2(v[3], h3, l3);
    uint2 hv = {pk(h0, h1), pk(h2, h3)};
    uint2 lv = {pk(l0, l1), pk(l2, l3)};
    *reinterpret_cast<uint2*>(dh + (size_t)r * ldd + cofs + c4 * 4) = hv;
    *reinterpret_cast<uint2*>(dl + (size_t)r * ldd + cofs + c4 * 4) = lv;
}

__global__ __launch_bounds__(128)
void segmean_kernel(const float* __restrict__ hid, const int* __restrict__ mol_ids,
                    float* __restrict__ out, int n_atoms)
{
    const int m = blockIdx.x, h4 = threadIdx.x;
    int lo = 0, hi = n_atoms;
    while (lo < hi) { int mid = (lo + hi) >> 1; if (mol_ids[mid] < m) lo = mid + 1; else hi = mid; }
    const int start = lo;
    hi = n_atoms;
    while (lo < hi) { int mid = (lo + hi) >> 1; if (mol_ids[mid] < m + 1) lo = mid + 1; else hi = mid; }
    const int end = lo;
    const int cnt = end - start;
    const float inv = cnt > 0 ? 1.f / (float)cnt : 0.f;
    float4 s = {0.f, 0.f, 0.f, 0.f};
    for (int a = start; a < end; ++a) {
        const float4 v = *reinterpret_cast<const float4*>(hid + (size_t)a * HIDDEN + h4 * 4);
        s.x += v.x; s.y += v.y; s.z += v.z; s.w += v.w;
    }
    s.x *= inv; s.y *= inv; s.z *= inv; s.w *= inv;
    *reinterpret_cast<float4*>(out + (size_t)m * HIDDEN + h4 * 4) = s;
}

// ---------------- launch ----------------
extern "C" void kernel_launch(void* const* d_in, const int* in_sizes, int n_in,
                              void* d_out, int out_size)
{
    const float* f_atoms = (const float*)d_in[0];
    const float* f_bonds = (const float*)d_in[1];
    const int*   a2b     = (const int*)  d_in[2];
    const int*   b2a     = (const int*)  d_in[3];
    const int*   b2revb  = (const int*)  d_in[4];
    const int*   mol_ids = (const int*)  d_in[5];
    const float* W_i     = (const float*)d_in[6];
    const float* W_h     = (const float*)d_in[7];
    const float* W_o     = (const float*)d_in[8];
    const float* b_o     = (const float*)d_in[9];

    const int n_atoms   = in_sizes[5];
    const int n_bonds   = in_sizes[3];
    const int bond_fdim = in_sizes[6] / HIDDEN;            // 147
    const int atom_fdim = in_sizes[8] / HIDDEN - HIDDEN;   // 133
    const int n_mols    = out_size / HIDDEN;
    float* out = (float*)d_out;

    float *p_inp, *p_msg, *p_amsg, *p_hid;
    __half *p_Ahi, *p_Alo, *p_CatHi, *p_CatLo, *p_WiH, *p_WhH, *p_WoH;
    cudaGetSymbolAddress((void**)&p_inp,  g_inp);
    cudaGetSymbolAddress((void**)&p_msg,  g_msg);
    cudaGetSymbolAddress((void**)&p_amsg, g_amsg);
    cudaGetSymbolAddress((void**)&p_hid,  g_hid);
    cudaGetSymbolAddress((void**)&p_Ahi,  g_Ahi);
    cudaGetSymbolAddress((void**)&p_Alo,  g_Alo);
    cudaGetSymbolAddress((void**)&p_CatHi, g_CatHi);
    cudaGetSymbolAddress((void**)&p_CatLo, g_CatLo);
    cudaGetSymbolAddress((void**)&p_WiH,  g_WiH);
    cudaGetSymbolAddress((void**)&p_WhH,  g_WhH);
    cudaGetSymbolAddress((void**)&p_WoH,  g_WoH);

    cudaFuncSetAttribute(gemm_hmma2<0>, cudaFuncAttributeMaxDynamicSharedMemorySize, SMEM_SZ);
    cudaFuncSetAttribute(gemm_hmma2<1>, cudaFuncAttributeMaxDynamicSharedMemorySize, SMEM_SZ);
    cudaFuncSetAttribute(gemm_hmma2<2>, cudaFuncAttributeMaxDynamicSharedMemorySize, SMEM_SZ);

    // [0] all conversions (weights + rows) in one launch
    const int conv_elems = 512 * (KW1 + 512 + 512 + KW1) + (NBP + NAP) * 40;
    conv_all<<<(conv_elems + 255) / 256, 256>>>(
        W_i, W_h, W_o, f_bonds, f_atoms,
        p_WiH, p_WhH, p_WoH,
        p_Ahi, p_Alo, p_CatHi, p_CatLo,
        bond_fdim, atom_fdim, n_bonds, n_atoms);

    // [1] GEMM0: inp = f_bonds @ W_i  (raw; msg_0 = relu(inp) applied on read)
    gemm_hmma2<0><<<dim3(4, NBP / 128), 256, SMEM_SZ>>>(
        p_Ahi, p_Alo, HIDDEN, p_WiH, KW1, KW1,
        nullptr, nullptr, p_inp);

    // [2..] 4 message-passing iterations; z_t stored raw, relu on read
    const float* curmsg = p_inp;
    for (int it = 0; it < 4; ++it) {
        aggregate_f32<<<n_atoms, 128>>>(curmsg, a2b, p_amsg);
        combine_k<<<NBP, 128>>>(p_amsg, curmsg, b2a, b2revb, p_Ahi, p_Alo, n_bonds);
        gemm_hmma2<1><<<dim3(4, NBP / 128), 256, SMEM_SZ>>>(
            p_Ahi, p_Alo, HIDDEN, p_WhH, 512, 512,
            p_inp, nullptr, p_msg);
        curmsg = p_msg;
    }

    // final aggregation (relu on read) -> concat A cols 0..511
    aggregate_f16<<<NAP, 128>>>(p_msg, a2b, p_CatHi, p_CatLo, n_atoms);

    // atom_hiddens = relu([amsg | f_atoms] @ Wo_cat + b_o)
    gemm_hmma2<2><<<dim3(4, NAP / 128), 256, SMEM_SZ>>>(
        p_CatHi, p_CatLo, KWO, p_WoH, KWO, KWO,
        nullptr, b_o, p_hid);

    segmean_kernel<<<n_mols, 128>>>(p_hid, mol_ids, out, n_atoms);
}